// round 5
// baseline (speedup 1.0000x reference)
#include <cuda_runtime.h>
#include <cuda_bf16.h>
#include <cstdint>

// ---------------------------------------------------------------------------
// ROIAlignPooler (3D, 4-level FPN) for B200 (sm_100a)
//
//   1. Fused transpose: all 4 levels NCDHW -> N DHW C (channel-last scratch).
//   2. Main kernel: 1024 blocks = ROI x (2 cell-halves) x (2 channel-halves),
//      192 threads, 7 blocks/SM -> near-perfect wave balance.
//      Per-block tap tables: per-dim merged (dup coords merged, zeros pruned),
//      y*x fused into 49 flat (offset, wy*wx) lists PADDED to multiples of 4.
//      Inner loop: 4 taps/chunk -> 2 LDS.128 + 4 independent LDG.128 (MLP 4).
//   3. Warp: 4 cells x 8 lanes x float4 (32 ch) -> 128B/line per cell region.
//   4. Output staged in shared [32][173], coalesced row writeout.
// ---------------------------------------------------------------------------

#define NROI    256
#define C_CH    64
#define CELLS   343
#define CELLS_H 172
#define OUT_PER_ROI (C_CH * CELLS)   // 21952

__device__ __align__(16) float g_t0[2 * 40 * 40 * 40 * C_CH];
__device__ __align__(16) float g_t1[2 * 20 * 20 * 20 * C_CH];
__device__ __align__(16) float g_t2[2 * 10 * 10 * 10 * C_CH];
__device__ __align__(16) float g_t3[2 * 5 * 5 * 5 * C_CH];

// ---------------------------------------------------------------------------
__global__ __launch_bounds__(1024)
void transpose_all_kernel(const float* __restrict__ x0,
                          const float* __restrict__ x1,
                          const float* __restrict__ x2,
                          const float* __restrict__ x3) {
    __shared__ float tile[32][133];

    const int bx = blockIdx.x;
    const float* src; float* dst; int DHW, spTiles, t0;
    if (bx < 2000)      { src = x0; dst = g_t0; DHW = 64000; spTiles = 500; t0 = bx; }
    else if (bx < 2252) { src = x1; dst = g_t1; DHW = 8000;  spTiles = 63;  t0 = bx - 2000; }
    else if (bx < 2284) { src = x2; dst = g_t2; DHW = 1000;  spTiles = 8;   t0 = bx - 2252; }
    else                { src = x3; dst = g_t3; DHW = 125;   spTiles = 1;   t0 = bx - 2284; }

    const int st = t0 % spTiles;
    const int t1 = t0 / spTiles;
    const int cg = t1 & 1;
    const int b  = t1 >> 1;
    const int cBase = cg * 32;
    const int sBase = st * 128;
    const int tx = threadIdx.x, ty = threadIdx.y;

    if ((DHW & 3) == 0) {
        int sp4 = sBase + 4 * tx;
        if (sp4 < DHW) {
            const float4 v = *(const float4*)(
                src + (size_t)(b * C_CH + cBase + ty) * DHW + sp4);
            tile[ty][4 * tx + 0] = v.x;
            tile[ty][4 * tx + 1] = v.y;
            tile[ty][4 * tx + 2] = v.z;
            tile[ty][4 * tx + 3] = v.w;
        }
    } else {
#pragma unroll
        for (int k = 0; k < 4; k++) {
            int sp = sBase + 32 * k + tx;
            if (sp < DHW)
                tile[ty][32 * k + tx] =
                    src[(size_t)(b * C_CH + cBase + ty) * DHW + sp];
        }
    }
    __syncthreads();
#pragma unroll
    for (int k = 0; k < 4; k++) {
        int sp = sBase + 32 * k + ty;
        if (sp < DHW)
            dst[((size_t)b * DHW + sp) * C_CH + cBase + tx] = tile[tx][32 * k + ty];
    }
}

// ---------------------------------------------------------------------------
__device__ __forceinline__ void dim_taps(float start, float bin, int o, int Dsz,
                                         int stride, int* to, float* tw) {
#pragma unroll
    for (int r = 0; r < 2; r++) {
        float c = start + ((float)(2 * o + r) + 0.5f) * 0.5f * bin;
        float valid = (c > -1.0f && c < (float)Dsz) ? 0.5f : 0.0f;
        c = fminf(fmaxf(c, 0.0f), (float)Dsz - 1.0f);
        float low = floorf(c);
        int li = (int)low;
        int hi = min(li + 1, Dsz - 1);
        float f = c - low;
        to[2 * r]     = li * stride;
        tw[2 * r]     = (1.0f - f) * valid;
        to[2 * r + 1] = hi * stride;
        tw[2 * r + 1] = f * valid;
    }
}

// ---------------------------------------------------------------------------
// Main kernel: 1024 blocks (ROI x cell-half x ch-half), 192 threads, 7/SM.
// ---------------------------------------------------------------------------
__global__ __launch_bounds__(192, 7)
void roi_align_kernel(const float* __restrict__ boxes, float* __restrict__ out) {
    __shared__ int    s_cnt[3][7];
    __shared__ int    s_off[3][7][4];
    __shared__ float  s_wt [3][7][4];
    __shared__ int    s_nyx[49];                      // padded list length (mult of 4)
    __shared__ __align__(16) float2 s_yx[49][16];     // (.x = offset bits, .y = wy*wx)
    __shared__ float  s_o[32 * 173];                  // [ch][cell] staging (pad 173)

    const int bx       = blockIdx.x;
    const int r        = bx >> 2;
    const int ch2      = bx & 1;
    const int cellh    = (bx >> 1) & 1;
    const int cellBase = cellh * CELLS_H;
    const int nCells   = cellh ? (CELLS - CELLS_H) : CELLS_H;  // 171 : 172
    const int b        = r >> 7;                      // nb = 128

    const float bz1 = boxes[r * 6 + 0];
    const float by1 = boxes[r * 6 + 1];
    const float bx1 = boxes[r * 6 + 2];
    const float bz2 = boxes[r * 6 + 3];
    const float by2 = boxes[r * 6 + 4];
    const float bx2 = boxes[r * 6 + 5];

    const float area = (bz2 - bz1 + 1.0f) * (by2 - by1 + 1.0f) * (bx2 - bx1 + 1.0f);
    const float s    = sqrtf(area);
    float lf = floorf(4.0f + log2f(s / 224.0f + 1e-6f));
    lf = fminf(fmaxf(lf, 2.0f), 5.0f);
    const int lvl = (int)lf - 2;

    const float* ft; int Dsz; float scale;
    if (lvl == 0)      { ft = g_t0; Dsz = 40; scale = 0.25f;    }
    else if (lvl == 1) { ft = g_t1; Dsz = 20; scale = 0.125f;   }
    else if (lvl == 2) { ft = g_t2; Dsz = 10; scale = 0.0625f;  }
    else               { ft = g_t3; Dsz = 5;  scale = 0.03125f; }

    const int DHW     = Dsz * Dsz * Dsz;
    const int strideZ = Dsz * Dsz * C_CH;
    const int strideY = Dsz * C_CH;

    const float z1 = bz1 * scale, y1 = by1 * scale, x1 = bx1 * scale;
    const float binz = fmaxf(bz2 * scale - z1, 1.0f) * (1.0f / 7.0f);
    const float biny = fmaxf(by2 * scale - y1, 1.0f) * (1.0f / 7.0f);
    const float binx = fmaxf(bx2 * scale - x1, 1.0f) * (1.0f / 7.0f);

    const int tid = threadIdx.x;

    // ---- phase 1: per-dim merged tap tables (21 threads) ----
    if (tid < 21) {
        const int dim = tid / 7;
        const int o   = tid - dim * 7;
        const float start  = (dim == 0) ? z1 : (dim == 1) ? y1 : x1;
        const float bin    = (dim == 0) ? binz : (dim == 1) ? biny : binx;
        const int   stride = (dim == 0) ? strideZ : (dim == 1) ? strideY : C_CH;

        int to[4]; float tw[4];
        dim_taps(start, bin, o, Dsz, stride, to, tw);

        int n = 0; int uo[4]; float uw[4];
#pragma unroll
        for (int t = 0; t < 4; t++) {
            if (tw[t] != 0.0f) {
                bool found = false;
#pragma unroll
                for (int j = 0; j < 4; j++) {
                    if (j < n && uo[j] == to[t]) { uw[j] += tw[t]; found = true; }
                }
                if (!found) { uo[n] = to[t]; uw[n] = tw[t]; n++; }
            }
        }
        s_cnt[dim][o] = n;
#pragma unroll
        for (int j = 0; j < 4; j++) {
            if (j < n) { s_off[dim][o][j] = uo[j]; s_wt[dim][o][j] = uw[j]; }
        }
    }
    __syncthreads();

    // ---- phase 2: fuse y*x into flat lists, padded to multiple of 4 ----
    if (tid < 49) {
        const int oy = tid / 7;
        const int ox = tid - oy * 7;
        const int ny = s_cnt[1][oy];
        const int nx = s_cnt[2][ox];
        int m = 0;
        for (int j = 0; j < ny; j++) {
            const int   yo = s_off[1][oy][j];
            const float wy = s_wt[1][oy][j];
            for (int k = 0; k < nx; k++) {
                s_yx[tid][m] = make_float2(
                    __int_as_float(yo + s_off[2][ox][k]),
                    wy * s_wt[2][ox][k]);
                m++;
            }
        }
        const int m4 = (m + 3) & ~3;
        for (; m < m4; m++)
            s_yx[tid][m] = make_float2(__int_as_float(0), 0.0f);
        s_nyx[tid] = m4;
    }
    __syncthreads();

    const int lane = tid & 31;
    const int warp = tid >> 5;       // 0..5
    const int g = lane >> 3;         // cell subgroup 0..3
    const int q = lane & 7;          // channel quad within 32-ch half

    const float* base = ft + (size_t)b * DHW * C_CH + ch2 * 32 + 4 * q;

    for (int cb = 4 * warp; cb < nCells; cb += 24) {
        const int cl  = cb + g;
        const int cc  = min(cl, nCells - 1);
        const int gc  = cellBase + cc;
        const int oz  = gc / 49;
        const int rem = gc - oz * 49;

        const int nz  = s_cnt[0][oz];
        const int m4  = s_nyx[rem];
        const float2* lst = s_yx[rem];

        float a0 = 0.f, a1 = 0.f, a2 = 0.f, a3 = 0.f;
        for (int i = 0; i < nz; i++) {
            const float wz = s_wt[0][oz][i];
            const float* bz = base + s_off[0][oz][i];
            for (int t = 0; t < m4; t += 4) {
                const float4 e01 = *(const float4*)(lst + t);
                const float4 e23 = *(const float4*)(lst + t + 2);
                const float4 v0 = *(const float4*)(bz + __float_as_int(e01.x));
                const float4 v1 = *(const float4*)(bz + __float_as_int(e01.z));
                const float4 v2 = *(const float4*)(bz + __float_as_int(e23.x));
                const float4 v3 = *(const float4*)(bz + __float_as_int(e23.z));
                const float w0 = wz * e01.y;
                const float w1 = wz * e01.w;
                const float w2 = wz * e23.y;
                const float w3 = wz * e23.w;
                a0 = fmaf(w0, v0.x, a0); a1 = fmaf(w0, v0.y, a1);
                a2 = fmaf(w0, v0.z, a2); a3 = fmaf(w0, v0.w, a3);
                a0 = fmaf(w1, v1.x, a0); a1 = fmaf(w1, v1.y, a1);
                a2 = fmaf(w1, v1.z, a2); a3 = fmaf(w1, v1.w, a3);
                a0 = fmaf(w2, v2.x, a0); a1 = fmaf(w2, v2.y, a1);
                a2 = fmaf(w2, v2.z, a2); a3 = fmaf(w2, v2.w, a3);
                a0 = fmaf(w3, v3.x, a0); a1 = fmaf(w3, v3.y, a1);
                a2 = fmaf(w3, v3.z, a2); a3 = fmaf(w3, v3.w, a3);
            }
        }

        if (cl < nCells) {
            s_o[(4 * q + 0) * 173 + cl] = a0;
            s_o[(4 * q + 1) * 173 + cl] = a1;
            s_o[(4 * q + 2) * 173 + cl] = a2;
            s_o[(4 * q + 3) * 173 + cl] = a3;
        }
    }

    __syncthreads();

    // writeout: channels [ch2*32, +32), cells [cellBase, cellBase+nCells)
    float* op = out + (size_t)r * OUT_PER_ROI + (ch2 * 32) * CELLS + cellBase;
#pragma unroll 8
    for (int c = 0; c < 32; c++) {
        if (tid < nCells)
            op[c * CELLS + tid] = s_o[c * 173 + tid];
    }
}

// ---------------------------------------------------------------------------
extern "C" void kernel_launch(void* const* d_in, const int* in_sizes, int n_in,
                              void* d_out, int out_size) {
    const float* x0    = (const float*)d_in[0];
    const float* x1    = (const float*)d_in[1];
    const float* x2    = (const float*)d_in[2];
    const float* x3    = (const float*)d_in[3];
    const float* boxes = (const float*)d_in[4];

    transpose_all_kernel<<<2288, dim3(32, 32)>>>(x0, x1, x2, x3);

    roi_align_kernel<<<NROI * 4, 192>>>(boxes, (float*)d_out);
}

// round 6
// speedup vs baseline: 1.0349x; 1.0349x over previous
#include <cuda_runtime.h>
#include <cuda_bf16.h>
#include <cstdint>

// ---------------------------------------------------------------------------
// ROIAlignPooler (3D, 4-level FPN) for B200 (sm_100a)
//
//   1. Fused transpose: all 4 levels NCDHW -> N DHW C; float4 loads AND
//      float4 stores (conflict-free smem patterns) where DHW % 4 == 0.
//   2. Main kernel: 1024 blocks = ROI x 4 cell-quarters, 192 threads,
//      7 blocks/SM -> single wave, ~1% imbalance. Full 64 channels per
//      block; warp = 2 cells x 16 lanes x float4 (R4 layout preserved).
//      Per-block tap tables: per-dim merged, y*x fused into 49 flat
//      (offset, wy*wx) lists padded to multiples of 4.
//      Inner loop: 4 taps/chunk -> 2 LDS.128 + 4 independent LDG.128.
//   3. Output staged in shared [64][89], flattened coalesced writeout.
// ---------------------------------------------------------------------------

#define NROI    256
#define C_CH    64
#define CELLS   343
#define QCELL   88          // cells per quarter (last = 79)
#define SPAD    89          // staging row pitch (odd -> 2-way max conflict)
#define OUT_PER_ROI (C_CH * CELLS)   // 21952

__device__ __align__(16) float g_t0[2 * 40 * 40 * 40 * C_CH];
__device__ __align__(16) float g_t1[2 * 20 * 20 * 20 * C_CH];
__device__ __align__(16) float g_t2[2 * 10 * 10 * 10 * C_CH];
__device__ __align__(16) float g_t3[2 * 5 * 5 * 5 * C_CH];

// ---------------------------------------------------------------------------
// Fused transpose: src[b][c][sp] -> dst[b][sp][c], all levels in one launch.
// ---------------------------------------------------------------------------
__global__ __launch_bounds__(1024)
void transpose_all_kernel(const float* __restrict__ x0,
                          const float* __restrict__ x1,
                          const float* __restrict__ x2,
                          const float* __restrict__ x3) {
    __shared__ float tile[32][133];

    const int bx = blockIdx.x;
    const float* src; float* dst; int DHW, spTiles, t0;
    if (bx < 2000)      { src = x0; dst = g_t0; DHW = 64000; spTiles = 500; t0 = bx; }
    else if (bx < 2252) { src = x1; dst = g_t1; DHW = 8000;  spTiles = 63;  t0 = bx - 2000; }
    else if (bx < 2284) { src = x2; dst = g_t2; DHW = 1000;  spTiles = 8;   t0 = bx - 2252; }
    else                { src = x3; dst = g_t3; DHW = 125;   spTiles = 1;   t0 = bx - 2284; }

    const int st = t0 % spTiles;
    const int t1 = t0 / spTiles;
    const int cg = t1 & 1;
    const int b  = t1 >> 1;
    const int cBase = cg * 32;
    const int sBase = st * 128;
    const int tx = threadIdx.x, ty = threadIdx.y;

    if ((DHW & 3) == 0) {
        // float4 global load: thread (tx,ty) covers sp [sBase+4tx, +4)
        int sp4 = sBase + 4 * tx;
        if (sp4 < DHW) {
            const float4 v = *(const float4*)(
                src + (size_t)(b * C_CH + cBase + ty) * DHW + sp4);
            tile[ty][4 * tx + 0] = v.x;
            tile[ty][4 * tx + 1] = v.y;
            tile[ty][4 * tx + 2] = v.z;
            tile[ty][4 * tx + 3] = v.w;
        }
        __syncthreads();
        // float4 global store: thread t -> sp = sBase + t/8, ch quad = t&7
        const int t  = ty * 32 + tx;
        const int spi = t >> 3;
        const int qc  = t & 7;
        const int sp  = sBase + spi;
        if (sp < DHW) {
            float4 v;
            v.x = tile[4 * qc + 0][spi];
            v.y = tile[4 * qc + 1][spi];
            v.z = tile[4 * qc + 2][spi];
            v.w = tile[4 * qc + 3][spi];
            *(float4*)(dst + ((size_t)b * DHW + sp) * C_CH + cBase + 4 * qc) = v;
        }
    } else {
#pragma unroll
        for (int k = 0; k < 4; k++) {
            int sp = sBase + 32 * k + tx;
            if (sp < DHW)
                tile[ty][32 * k + tx] =
                    src[(size_t)(b * C_CH + cBase + ty) * DHW + sp];
        }
        __syncthreads();
#pragma unroll
        for (int k = 0; k < 4; k++) {
            int sp = sBase + 32 * k + ty;
            if (sp < DHW)
                dst[((size_t)b * DHW + sp) * C_CH + cBase + tx] = tile[tx][32 * k + ty];
        }
    }
}

// ---------------------------------------------------------------------------
__device__ __forceinline__ void dim_taps(float start, float bin, int o, int Dsz,
                                         int stride, int* to, float* tw) {
#pragma unroll
    for (int r = 0; r < 2; r++) {
        float c = start + ((float)(2 * o + r) + 0.5f) * 0.5f * bin;
        float valid = (c > -1.0f && c < (float)Dsz) ? 0.5f : 0.0f;
        c = fminf(fmaxf(c, 0.0f), (float)Dsz - 1.0f);
        float low = floorf(c);
        int li = (int)low;
        int hi = min(li + 1, Dsz - 1);
        float f = c - low;
        to[2 * r]     = li * stride;
        tw[2 * r]     = (1.0f - f) * valid;
        to[2 * r + 1] = hi * stride;
        tw[2 * r + 1] = f * valid;
    }
}

// ---------------------------------------------------------------------------
// Main kernel: 1024 blocks (ROI x cell-quarter), 192 threads, 7 blocks/SM.
// ---------------------------------------------------------------------------
__global__ __launch_bounds__(192, 7)
void roi_align_kernel(const float* __restrict__ boxes, float* __restrict__ out) {
    __shared__ int    s_cnt[3][7];
    __shared__ int    s_off[3][7][4];
    __shared__ float  s_wt [3][7][4];
    __shared__ int    s_nyx[49];                      // padded length (mult of 4)
    __shared__ __align__(16) float2 s_yx[49][16];     // (.x = offset bits, .y = wy*wx)
    __shared__ float  s_o[C_CH * SPAD];               // [64][89] staging

    const int bx       = blockIdx.x;
    const int r        = bx >> 2;
    const int quarter  = bx & 3;
    const int cellBase = quarter * QCELL;
    const int nc       = min(QCELL, CELLS - cellBase);   // 88,88,88,79
    const int b        = r >> 7;                         // nb = 128

    const float bz1 = boxes[r * 6 + 0];
    const float by1 = boxes[r * 6 + 1];
    const float bx1 = boxes[r * 6 + 2];
    const float bz2 = boxes[r * 6 + 3];
    const float by2 = boxes[r * 6 + 4];
    const float bx2 = boxes[r * 6 + 5];

    const float area = (bz2 - bz1 + 1.0f) * (by2 - by1 + 1.0f) * (bx2 - bx1 + 1.0f);
    const float s    = sqrtf(area);
    float lf = floorf(4.0f + log2f(s / 224.0f + 1e-6f));
    lf = fminf(fmaxf(lf, 2.0f), 5.0f);
    const int lvl = (int)lf - 2;

    const float* ft; int Dsz; float scale;
    if (lvl == 0)      { ft = g_t0; Dsz = 40; scale = 0.25f;    }
    else if (lvl == 1) { ft = g_t1; Dsz = 20; scale = 0.125f;   }
    else if (lvl == 2) { ft = g_t2; Dsz = 10; scale = 0.0625f;  }
    else               { ft = g_t3; Dsz = 5;  scale = 0.03125f; }

    const int DHW     = Dsz * Dsz * Dsz;
    const int strideZ = Dsz * Dsz * C_CH;
    const int strideY = Dsz * C_CH;

    const float z1 = bz1 * scale, y1 = by1 * scale, x1 = bx1 * scale;
    const float binz = fmaxf(bz2 * scale - z1, 1.0f) * (1.0f / 7.0f);
    const float biny = fmaxf(by2 * scale - y1, 1.0f) * (1.0f / 7.0f);
    const float binx = fmaxf(bx2 * scale - x1, 1.0f) * (1.0f / 7.0f);

    const int tid = threadIdx.x;

    // ---- phase 1: per-dim merged tap tables (21 threads) ----
    if (tid < 21) {
        const int dim = tid / 7;
        const int o   = tid - dim * 7;
        const float start  = (dim == 0) ? z1 : (dim == 1) ? y1 : x1;
        const float bin    = (dim == 0) ? binz : (dim == 1) ? biny : binx;
        const int   stride = (dim == 0) ? strideZ : (dim == 1) ? strideY : C_CH;

        int to[4]; float tw[4];
        dim_taps(start, bin, o, Dsz, stride, to, tw);

        int n = 0; int uo[4]; float uw[4];
#pragma unroll
        for (int t = 0; t < 4; t++) {
            if (tw[t] != 0.0f) {
                bool found = false;
#pragma unroll
                for (int j = 0; j < 4; j++) {
                    if (j < n && uo[j] == to[t]) { uw[j] += tw[t]; found = true; }
                }
                if (!found) { uo[n] = to[t]; uw[n] = tw[t]; n++; }
            }
        }
        s_cnt[dim][o] = n;
#pragma unroll
        for (int j = 0; j < 4; j++) {
            if (j < n) { s_off[dim][o][j] = uo[j]; s_wt[dim][o][j] = uw[j]; }
        }
    }
    __syncthreads();

    // ---- phase 2: fuse y*x into flat lists, padded to multiple of 4 ----
    if (tid < 49) {
        const int oy = tid / 7;
        const int ox = tid - oy * 7;
        const int ny = s_cnt[1][oy];
        const int nx = s_cnt[2][ox];
        int m = 0;
        for (int j = 0; j < ny; j++) {
            const int   yo = s_off[1][oy][j];
            const float wy = s_wt[1][oy][j];
            for (int k = 0; k < nx; k++) {
                s_yx[tid][m] = make_float2(
                    __int_as_float(yo + s_off[2][ox][k]),
                    wy * s_wt[2][ox][k]);
                m++;
            }
        }
        const int m4 = (m + 3) & ~3;
        for (; m < m4; m++)
            s_yx[tid][m] = make_float2(__int_as_float(0), 0.0f);
        s_nyx[tid] = m4;
    }
    __syncthreads();

    const int lane = tid & 31;
    const int warp = tid >> 5;       // 0..5
    const int h = lane >> 4;         // cell half (0/1)
    const int q = lane & 15;         // channel quad -> channels 4q..4q+3

    const float* base = ft + (size_t)b * DHW * C_CH + 4 * q;

    for (int cb = 2 * warp; cb < nc; cb += 12) {
        const int cl  = cb + h;
        const int cc  = min(cl, nc - 1);
        const int gc  = cellBase + cc;
        const int oz  = gc / 49;
        const int rem = gc - oz * 49;

        const int nz  = s_cnt[0][oz];
        const int m4  = s_nyx[rem];
        const float2* lst = s_yx[rem];

        float a0 = 0.f, a1 = 0.f, a2 = 0.f, a3 = 0.f;
        for (int i = 0; i < nz; i++) {
            const float wz = s_wt[0][oz][i];
            const float* bz = base + s_off[0][oz][i];
            for (int t = 0; t < m4; t += 4) {
                const float4 e01 = *(const float4*)(lst + t);
                const float4 e23 = *(const float4*)(lst + t + 2);
                const float4 v0 = *(const float4*)(bz + __float_as_int(e01.x));
                const float4 v1 = *(const float4*)(bz + __float_as_int(e01.z));
                const float4 v2 = *(const float4*)(bz + __float_as_int(e23.x));
                const float4 v3 = *(const float4*)(bz + __float_as_int(e23.z));
                const float w0 = wz * e01.y;
                const float w1 = wz * e01.w;
                const float w2 = wz * e23.y;
                const float w3 = wz * e23.w;
                a0 = fmaf(w0, v0.x, a0); a1 = fmaf(w0, v0.y, a1);
                a2 = fmaf(w0, v0.z, a2); a3 = fmaf(w0, v0.w, a3);
                a0 = fmaf(w1, v1.x, a0); a1 = fmaf(w1, v1.y, a1);
                a2 = fmaf(w1, v1.z, a2); a3 = fmaf(w1, v1.w, a3);
                a0 = fmaf(w2, v2.x, a0); a1 = fmaf(w2, v2.y, a1);
                a2 = fmaf(w2, v2.z, a2); a3 = fmaf(w2, v2.w, a3);
                a0 = fmaf(w3, v3.x, a0); a1 = fmaf(w3, v3.y, a1);
                a2 = fmaf(w3, v3.z, a2); a3 = fmaf(w3, v3.w, a3);
            }
        }

        if (cl < nc) {
            s_o[(4 * q + 0) * SPAD + cl] = a0;
            s_o[(4 * q + 1) * SPAD + cl] = a1;
            s_o[(4 * q + 2) * SPAD + cl] = a2;
            s_o[(4 * q + 3) * SPAD + cl] = a3;
        }
    }

    __syncthreads();

    // writeout: 64 channel rows of nc cells starting at [r][0][cellBase]
    float* op = out + (size_t)r * OUT_PER_ROI + cellBase;
    const int total = C_CH * nc;
    for (int i = tid; i < total; i += 192) {
        const int c  = i / nc;
        const int cl = i - c * nc;
        op[c * CELLS + cl] = s_o[c * SPAD + cl];
    }
}

// ---------------------------------------------------------------------------
extern "C" void kernel_launch(void* const* d_in, const int* in_sizes, int n_in,
                              void* d_out, int out_size) {
    const float* x0    = (const float*)d_in[0];
    const float* x1    = (const float*)d_in[1];
    const float* x2    = (const float*)d_in[2];
    const float* x3    = (const float*)d_in[3];
    const float* boxes = (const float*)d_in[4];

    transpose_all_kernel<<<2288, dim3(32, 32)>>>(x0, x1, x2, x3);

    roi_align_kernel<<<NROI * 4, 192>>>(boxes, (float*)d_out);
}